// round 11
// baseline (speedup 1.0000x reference)
#include <cuda_runtime.h>
#include <cuda_bf16.h>
#include <math.h>
#include <stdint.h>

// Problem constants
#define BB 2
#define SS 2048
#define DD 2048
#define NH 32
#define NKV 8
#define HD 64
#define GG (NH / NKV)   // 4
#define KX (3 * DD)     // expanded K = 6144

// ---------------- scratch (static __device__, no allocations) ----------------
__device__ float g_q[BB * SS * NH * HD];
__device__ float g_k[BB * SS * NKV * HD];
__device__ float g_v[BB * SS * NKV * HD];
__device__ float g_invf[HD / 2];

// split-bf16 expanded operands, PLANE layout along K:
//   A-side [M][3K]: cols [0,K)=hi, [K,2K)=lo, [2K,3K)=hi
//   B-side [N][3K]: cols [0,K)=hi, [K,2K)=hi, [2K,3K)=lo
// -> termwise products: hi*hi + lo*hi + hi*lo  (Markidis 3-term)
__device__ __nv_bfloat16 g_Xx[(size_t)BB * SS * KX];
__device__ __nv_bfloat16 g_attnx[(size_t)BB * SS * KX];
__device__ __nv_bfloat16 g_Wqx[(size_t)(NH * HD) * KX];
__device__ __nv_bfloat16 g_Wkx[(size_t)(NKV * HD) * KX];
__device__ __nv_bfloat16 g_Wvx[(size_t)(NKV * HD) * KX];
__device__ __nv_bfloat16 g_Wox[(size_t)DD * KX];

// ---------------- inv_freq table ---------------------------------------------
__global__ void invf_kernel()
{
    int i = threadIdx.x;
    if (i < HD / 2)
        g_invf[i] = (float)exp2(-(double)i * 0.41524101186092028); // log2(1e4)/32
}

// ---------------- helpers ----------------------------------------------------
__device__ __forceinline__ uint32_t smem_u32(const void* p) {
    uint32_t a;
    asm("{ .reg .u64 t; cvta.to.shared.u64 t, %1; cvt.u32.u64 %0, t; }"
        : "=r"(a) : "l"(p));
    return a;
}
#define CP_ASYNC16(dst, src) \
    asm volatile("cp.async.cg.shared.global [%0], [%1], 16;" \
                 :: "r"(dst), "l"(src) : "memory")
#define CP_COMMIT()  asm volatile("cp.async.commit_group;" ::: "memory")
#define CP_WAIT(n)   asm volatile("cp.async.wait_group %0;" :: "n"(n) : "memory")

#define MMA16816(C, A, B0, B1) \
    asm volatile("mma.sync.aligned.m16n8k16.row.col.f32.bf16.bf16.f32 " \
                 "{%0,%1,%2,%3}, {%4,%5,%6,%7}, {%8,%9}, {%0,%1,%2,%3};\n" \
                 : "+f"((C)[0]), "+f"((C)[1]), "+f"((C)[2]), "+f"((C)[3]) \
                 : "r"((A)[0]), "r"((A)[1]), "r"((A)[2]), "r"((A)[3]), \
                   "r"(B0), "r"(B1))

__device__ __forceinline__ uint32_t pack_bf16hi(float a, float b) {
    __nv_bfloat162 h;
    h.x = __float2bfloat16_rn(a);
    h.y = __float2bfloat16_rn(b);
    return *(uint32_t*)&h;
}
__device__ __forceinline__ uint32_t pack_bf16lo(float a, float b) {
    __nv_bfloat16 ha = __float2bfloat16_rn(a);
    __nv_bfloat16 hb = __float2bfloat16_rn(b);
    __nv_bfloat162 l;
    l.x = __float2bfloat16_rn(a - __bfloat162float(ha));
    l.y = __float2bfloat16_rn(b - __bfloat162float(hb));
    return *(uint32_t*)&l;
}

// fast e^x on the fma pipe (x <= 0), rel err ~3e-6
__device__ __forceinline__ float expf_fast(float x) {
    float y = x * 1.44269504088896f;
    y = fmaxf(y, -126.0f);
    float n = rintf(y);
    float f = y - n;
    float p = 1.33335581464e-3f;
    p = fmaf(p, f, 9.61812910763e-3f);
    p = fmaf(p, f, 5.55041086648e-2f);
    p = fmaf(p, f, 2.40226506959e-1f);
    p = fmaf(p, f, 6.93147180560e-1f);
    p = fmaf(p, f, 1.0f);
    float sc = __int_as_float(((int)n + 127) << 23);
    return p * sc;
}

// ---------------- split-bf16 expansion (plane layout, coalesced) -------------
// A [M,K] fp32 -> Ax [M,3K]: thread handles 8 consecutive k.
__global__ void expandA_kernel(const float* __restrict__ A,
                               __nv_bfloat16* __restrict__ Ax, int M, int K)
{
    int idx = blockIdx.x * blockDim.x + threadIdx.x;
    int total = M * (K / 8);
    if (idx >= total) return;
    int m  = idx / (K / 8);
    int k8 = (idx % (K / 8)) * 8;
    float4 x0 = *(const float4*)(A + (size_t)m * K + k8);
    float4 x1 = *(const float4*)(A + (size_t)m * K + k8 + 4);
    float v[8] = {x0.x, x0.y, x0.z, x0.w, x1.x, x1.y, x1.z, x1.w};
    __align__(16) uint32_t hi[4], lo[4];
#pragma unroll
    for (int j = 0; j < 4; j++) {
        hi[j] = pack_bf16hi(v[2 * j], v[2 * j + 1]);
        lo[j] = pack_bf16lo(v[2 * j], v[2 * j + 1]);
    }
    __nv_bfloat16* base = Ax + (size_t)m * 3 * K;
    *(uint4*)(base + k8)         = *(uint4*)hi;   // plane 0: hi
    *(uint4*)(base + K + k8)     = *(uint4*)lo;   // plane 1: lo
    *(uint4*)(base + 2 * K + k8) = *(uint4*)hi;   // plane 2: hi
}

// B [K,N] fp32 -> Bt [N,3K] (transposed, K-major planes [hi|hi|lo]):
// thread handles 16 consecutive k for one n; reads coalesced across n,
// writes 32B-aligned contiguous runs.
__global__ void expandBt_kernel(const float* __restrict__ B,
                                __nv_bfloat16* __restrict__ Bt, int K, int N)
{
    int idx = blockIdx.x * blockDim.x + threadIdx.x;
    int total = N * (K / 16);
    if (idx >= total) return;
    int n   = idx % N;
    int k16 = (idx / N) * 16;
    float v[16];
#pragma unroll
    for (int i = 0; i < 16; i++) v[i] = B[(size_t)(k16 + i) * N + n];
    __align__(16) uint32_t hi[8], lo[8];
#pragma unroll
    for (int j = 0; j < 8; j++) {
        hi[j] = pack_bf16hi(v[2 * j], v[2 * j + 1]);
        lo[j] = pack_bf16lo(v[2 * j], v[2 * j + 1]);
    }
    __nv_bfloat16* base = Bt + (size_t)n * 3 * K;
    *(uint4*)(base + k16)             = *(uint4*)(hi);       // plane 0: hi
    *(uint4*)(base + k16 + 8)         = *(uint4*)(hi + 4);
    *(uint4*)(base + K + k16)         = *(uint4*)(hi);       // plane 1: hi
    *(uint4*)(base + K + k16 + 8)     = *(uint4*)(hi + 4);
    *(uint4*)(base + 2 * K + k16)     = *(uint4*)(lo);       // plane 2: lo
    *(uint4*)(base + 2 * K + k16 + 8) = *(uint4*)(lo + 4);
}

// ---------------- mma.sync GEMM (mainloop unchanged from R8/R9) --------------
#define GST 40

__global__ __launch_bounds__(256)
void gemm_bf16_kernel(int M, int N, const __nv_bfloat16* __restrict__ A,
                      const __nv_bfloat16* __restrict__ Bt,
                      float* __restrict__ C)
{
    __shared__ __align__(16) __nv_bfloat16 sA[2][128 * GST];
    __shared__ __align__(16) __nv_bfloat16 sB[2][128 * GST];

    const int tid  = threadIdx.x;
    const int wid  = tid / 32;
    const int lane = tid % 32;
    const int warpM = wid / 2;
    const int warpN = wid % 2;
    const int g = lane >> 2;
    const int t = lane & 3;
    const int rowBase = warpM * 32;
    const int colBase = warpN * 64;

    const __nv_bfloat16* Ag = A  + (size_t)blockIdx.y * 128 * KX;
    const __nv_bfloat16* Bg = Bt + (size_t)blockIdx.x * 128 * KX;

    const int r0 = tid >> 2;
    const int c0 = (tid & 3) * 8;
    const int r1 = r0 + 64;

    const uint32_t sA0 = smem_u32(sA[0]), sA1 = smem_u32(sA[1]);
    const uint32_t sB0 = smem_u32(sB[0]), sB1 = smem_u32(sB[1]);
    const uint32_t dA0 = r0 * GST + c0, dA1 = r1 * GST + c0;

    float c[2][8][4];
#pragma unroll
    for (int mi = 0; mi < 2; mi++)
#pragma unroll
        for (int ni = 0; ni < 8; ni++)
#pragma unroll
            for (int r = 0; r < 4; r++) c[mi][ni][r] = 0.0f;

    const int NCH = KX / 32;

    CP_ASYNC16(sA0 + 2 * dA0, Ag + (size_t)r0 * KX + c0);
    CP_ASYNC16(sA0 + 2 * dA1, Ag + (size_t)r1 * KX + c0);
    CP_ASYNC16(sB0 + 2 * dA0, Bg + (size_t)r0 * KX + c0);
    CP_ASYNC16(sB0 + 2 * dA1, Bg + (size_t)r1 * KX + c0);
    CP_COMMIT();

    for (int ch = 0; ch < NCH; ch++) {
        if (ch + 1 < NCH) {
            const int kc = (ch + 1) * 32;
            const uint32_t a = ((ch + 1) & 1) ? sA1 : sA0;
            const uint32_t b = ((ch + 1) & 1) ? sB1 : sB0;
            CP_ASYNC16(a + 2 * dA0, Ag + (size_t)r0 * KX + kc + c0);
            CP_ASYNC16(a + 2 * dA1, Ag + (size_t)r1 * KX + kc + c0);
            CP_ASYNC16(b + 2 * dA0, Bg + (size_t)r0 * KX + kc + c0);
            CP_ASYNC16(b + 2 * dA1, Bg + (size_t)r1 * KX + kc + c0);
            CP_COMMIT();
            CP_WAIT(1);
        } else {
            CP_WAIT(0);
        }
        __syncthreads();

        const __nv_bfloat16* As = (ch & 1) ? sA[1] : sA[0];
        const __nv_bfloat16* Bs = (ch & 1) ? sB[1] : sB[0];

#pragma unroll
        for (int kk = 0; kk < 32; kk += 16) {
            uint32_t af[2][4], bfr[8][2];
#pragma unroll
            for (int mi = 0; mi < 2; mi++) {
                const __nv_bfloat16* p = As + (rowBase + mi * 16 + g) * GST + kk + 2 * t;
                af[mi][0] = *(const uint32_t*)p;
                af[mi][1] = *(const uint32_t*)(p + 8 * GST);
                af[mi][2] = *(const uint32_t*)(p + 8);
                af[mi][3] = *(const uint32_t*)(p + 8 * GST + 8);
            }
#pragma unroll
            for (int ni = 0; ni < 8; ni++) {
                const __nv_bfloat16* p = Bs + (colBase + ni * 8 + g) * GST + kk + 2 * t;
                bfr[ni][0] = *(const uint32_t*)p;
                bfr[ni][1] = *(const uint32_t*)(p + 8);
            }
#pragma unroll
            for (int mi = 0; mi < 2; mi++)
#pragma unroll
                for (int ni = 0; ni < 8; ni++)
                    MMA16816(c[mi][ni], af[mi], bfr[ni][0], bfr[ni][1]);
        }
        __syncthreads();
    }

    float* Cg = C + (size_t)blockIdx.y * 128 * N + (size_t)blockIdx.x * 128;
#pragma unroll
    for (int mi = 0; mi < 2; mi++) {
#pragma unroll
        for (int ni = 0; ni < 8; ni++) {
            int rr  = rowBase + mi * 16 + g;
            int col = colBase + ni * 8 + 2 * t;
            float2 lo = make_float2(c[mi][ni][0], c[mi][ni][1]);
            float2 hi = make_float2(c[mi][ni][2], c[mi][ni][3]);
            *(float2*)(Cg + (size_t)rr * N + col)       = lo;
            *(float2*)(Cg + (size_t)(rr + 8) * N + col) = hi;
        }
    }
}

// ---------------- RoPE (unchanged) -------------------------------------------
__global__ void rope_kernel(float* __restrict__ q, float* __restrict__ k, int total)
{
    int idx = blockIdx.x * blockDim.x + threadIdx.x;
    if (idx >= total) return;

    const int PER_ROW = (NH + NKV) * (HD / 2);
    int row  = idx / PER_ROW;
    int rem  = idx % PER_ROW;
    int slot = rem / (HD / 2);
    int fi   = rem % (HD / 2);
    int spos = row % SS;

    float invf = g_invf[fi];
    float ang  = (float)spos * invf;

    float n = rintf(ang * 0.15915494309189535f);
    float r = fmaf(n, -6.28318548202514648f, ang);
    r       = fmaf(n,  1.74845553e-7f, r);
    float c  = __cosf(r);
    float sn = __sinf(r);

    float* base;
    if (slot < NH) base = q + ((size_t)row * NH + slot) * HD;
    else           base = k + ((size_t)row * NKV + (slot - NH)) * HD;

    float x1 = base[fi];
    float x2 = base[fi + HD / 2];
    base[fi]          = x1 * c - x2 * sn;
    base[fi + HD / 2] = x2 * c + x1 * sn;
}

// ---------------- Tensor-core flash attention (split-bf16, causal, GQA) ------
// Epilogue writes DIRECTLY into the expanded attnx planes (fuses expandA).
#define FTS 72

__global__ __launch_bounds__(128)
void flash_mma_kernel(const float* __restrict__ Q,
                      const float* __restrict__ Kg,
                      const float* __restrict__ Vg,
                      __nv_bfloat16* __restrict__ AttnX)
{
    __shared__ __align__(16) __nv_bfloat16 sKh[64 * FTS];
    __shared__ __align__(16) __nv_bfloat16 sKl[64 * FTS];
    __shared__ __align__(16) __nv_bfloat16 sVh[64 * FTS];   // [d][key]
    __shared__ __align__(16) __nv_bfloat16 sVl[64 * FTS];

    const int tid = threadIdx.x;
    const int w    = tid >> 5;
    const int lane = tid & 31;
    const int g = lane >> 2, t = lane & 3;
    const int qt = blockIdx.x, h = blockIdx.y, b = blockIdx.z;
    const int rbase = qt * 64 + w * 16;
    const int kvh = h / GG;

    uint32_t qh[4][4], ql[4][4];
#pragma unroll
    for (int kk = 0; kk < 4; kk++) {
#pragma unroll
        for (int pt = 0; pt < 4; pt++) {
            int row = rbase + g + (pt & 1) * 8;
            int col = kk * 16 + 2 * t + (pt >> 1) * 8;
            const float* qp = Q + (((size_t)(b * SS + row)) * NH + h) * HD + col;
            float2 qv = *(const float2*)qp;
            float x0 = qv.x * 0.125f, x1 = qv.y * 0.125f;
            qh[kk][pt] = pack_bf16hi(x0, x1);
            ql[kk][pt] = pack_bf16lo(x0, x1);
        }
    }

    float o[8][4];
#pragma unroll
    for (int ni = 0; ni < 8; ni++)
#pragma unroll
        for (int j = 0; j < 4; j++) o[ni][j] = 0.0f;
    float m0 = -1e30f, m1 = -1e30f, l0 = 0.0f, l1 = 0.0f;

    const int ntiles = qt + 1;
    const int lr  = tid >> 1;
    const int lcg = (tid & 1) * 32;

    for (int kt = 0; kt < ntiles; kt++) {
        const int kbase = kt * 64;
        {
            const float* kp = Kg + (((size_t)(b * SS + kbase + lr)) * NKV + kvh) * HD + lcg;
            const float* vp = Vg + (((size_t)(b * SS + kbase + lr)) * NKV + kvh) * HD + lcg;
#pragma unroll
            for (int dd = 0; dd < 32; dd += 4) {
                float4 kv = *(const float4*)(kp + dd);
                float kvv[4] = {kv.x, kv.y, kv.z, kv.w};
                uint32_t* dsth = (uint32_t*)&sKh[lr * FTS + lcg + dd];
                uint32_t* dstl = (uint32_t*)&sKl[lr * FTS + lcg + dd];
                dsth[0] = pack_bf16hi(kvv[0], kvv[1]);
                dsth[1] = pack_bf16hi(kvv[2], kvv[3]);
                dstl[0] = pack_bf16lo(kvv[0], kvv[1]);
                dstl[1] = pack_bf16lo(kvv[2], kvv[3]);

                float4 vv = *(const float4*)(vp + dd);
                float vvv[4] = {vv.x, vv.y, vv.z, vv.w};
#pragma unroll
                for (int j = 0; j < 4; j++) {
                    __nv_bfloat16 hv = __float2bfloat16_rn(vvv[j]);
                    __nv_bfloat16 lv = __float2bfloat16_rn(vvv[j] - __bfloat162float(hv));
                    sVh[(lcg + dd + j) * FTS + lr] = hv;
                    sVl[(lcg + dd + j) * FTS + lr] = lv;
                }
            }
        }
        __syncthreads();

        float s[8][4];
#pragma unroll
        for (int ni = 0; ni < 8; ni++)
#pragma unroll
            for (int j = 0; j < 4; j++) s[ni][j] = 0.0f;

#pragma unroll
        for (int kk = 0; kk < 4; kk++) {
#pragma unroll
            for (int ni = 0; ni < 8; ni++) {
                const __nv_bfloat16* ph = sKh + (ni * 8 + g) * FTS + kk * 16 + 2 * t;
                const __nv_bfloat16* pl = sKl + (ni * 8 + g) * FTS + kk * 16 + 2 * t;
                uint32_t bh0 = *(const uint32_t*)ph;
                uint32_t bh1 = *(const uint32_t*)(ph + 8);
                uint32_t bl0 = *(const uint32_t*)pl;
                uint32_t bl1 = *(const uint32_t*)(pl + 8);
                MMA16816(s[ni], qh[kk], bh0, bh1);
                MMA16816(s[ni], qh[kk], bl0, bl1);
                MMA16816(s[ni], ql[kk], bh0, bh1);
            }
        }

        if (kt == ntiles - 1) {
#pragma unroll
            for (int ni = 0; ni < 8; ni++) {
#pragma unroll
                for (int j = 0; j < 4; j++) {
                    int key = kbase + ni * 8 + 2 * t + (j & 1);
                    int row = rbase + g + (j >> 1) * 8;
                    if (key > row) s[ni][j] = -1e30f;
                }
            }
        }

        float tm0 = -1e30f, tm1 = -1e30f;
#pragma unroll
        for (int ni = 0; ni < 8; ni++) {
            tm0 = fmaxf(tm0, fmaxf(s[ni][0], s[ni][1]));
            tm1 = fmaxf(tm1, fmaxf(s[ni][2], s[ni][3]));
        }
        tm0 = fmaxf(tm0, __shfl_xor_sync(0xFFFFFFFF, tm0, 1));
        tm0 = fmaxf(tm0, __shfl_xor_sync(0xFFFFFFFF, tm0, 2));
        tm1 = fmaxf(tm1, __shfl_xor_sync(0xFFFFFFFF, tm1, 1));
        tm1 = fmaxf(tm1, __shfl_xor_sync(0xFFFFFFFF, tm1, 2));

        float mn0 = fmaxf(m0, tm0), mn1 = fmaxf(m1, tm1);
        float c0 = expf_fast(m0 - mn0), c1 = expf_fast(m1 - mn1);
        l0 *= c0; l1 *= c1;
#pragma unroll
        for (int ni = 0; ni < 8; ni++) {
            o[ni][0] *= c0; o[ni][1] *= c0;
            o[ni][2] *= c1; o[ni][3] *= c1;
        }
        float rs0 = 0.0f, rs1 = 0.0f;
#pragma unroll
        for (int ni = 0; ni < 8; ni++) {
            s[ni][0] = expf_fast(s[ni][0] - mn0);
            s[ni][1] = expf_fast(s[ni][1] - mn0);
            s[ni][2] = expf_fast(s[ni][2] - mn1);
            s[ni][3] = expf_fast(s[ni][3] - mn1);
            rs0 += s[ni][0] + s[ni][1];
            rs1 += s[ni][2] + s[ni][3];
        }
        rs0 += __shfl_xor_sync(0xFFFFFFFF, rs0, 1);
        rs0 += __shfl_xor_sync(0xFFFFFFFF, rs0, 2);
        rs1 += __shfl_xor_sync(0xFFFFFFFF, rs1, 1);
        rs1 += __shfl_xor_sync(0xFFFFFFFF, rs1, 2);
        l0 += rs0; l1 += rs1;
        m0 = mn0; m1 = mn1;

#pragma unroll
        for (int kk = 0; kk < 4; kk++) {
            const float* s0 = s[2 * kk];
            const float* s1 = s[2 * kk + 1];
            uint32_t ah[4], al[4];
            ah[0] = pack_bf16hi(s0[0], s0[1]);  al[0] = pack_bf16lo(s0[0], s0[1]);
            ah[1] = pack_bf16hi(s0[2], s0[3]);  al[1] = pack_bf16lo(s0[2], s0[3]);
            ah[2] = pack_bf16hi(s1[0], s1[1]);  al[2] = pack_bf16lo(s1[0], s1[1]);
            ah[3] = pack_bf16hi(s1[2], s1[3]);  al[3] = pack_bf16lo(s1[2], s1[3]);
#pragma unroll
            for (int ni = 0; ni < 8; ni++) {
                const __nv_bfloat16* pvh = sVh + (ni * 8 + g) * FTS + kk * 16 + 2 * t;
                const __nv_bfloat16* pvl = sVl + (ni * 8 + g) * FTS + kk * 16 + 2 * t;
                uint32_t vh0 = *(const uint32_t*)pvh;
                uint32_t vh1 = *(const uint32_t*)(pvh + 8);
                uint32_t vl0 = *(const uint32_t*)pvl;
                uint32_t vl1 = *(const uint32_t*)(pvl + 8);
                MMA16816(o[ni], ah, vh0, vh1);
                MMA16816(o[ni], al, vh0, vh1);
                MMA16816(o[ni], ah, vl0, vl1);
            }
        }
        __syncthreads();
    }

    // ---- epilogue: write hi/lo planes of attnx directly (fused expandA) ----
    float i0 = 1.0f / l0, i1 = 1.0f / l1;
#pragma unroll
    for (int ni = 0; ni < 8; ni++) {
        int col = h * HD + ni * 8 + 2 * t;
        int row0 = rbase + g, row1 = rbase + g + 8;
        __nv_bfloat16* b0 = AttnX + (size_t)(b * SS + row0) * KX + col;
        __nv_bfloat16* b1 = AttnX + (size_t)(b * SS + row1) * KX + col;
        float v00 = o[ni][0] * i0, v01 = o[ni][1] * i0;
        float v10 = o[ni][2] * i1, v11 = o[ni][3] * i1;
        uint32_t h0 = pack_bf16hi(v00, v01), l0p = pack_bf16lo(v00, v01);
        uint32_t h1 = pack_bf16hi(v10, v11), l1p = pack_bf16lo(v10, v11);
        *(uint32_t*)(b0)          = h0;   // plane 0: hi
        *(uint32_t*)(b0 + DD)     = l0p;  // plane 1: lo
        *(uint32_t*)(b0 + 2 * DD) = h0;   // plane 2: hi
        *(uint32_t*)(b1)          = h1;
        *(uint32_t*)(b1 + DD)     = l1p;
        *(uint32_t*)(b1 + 2 * DD) = h1;
    }
}

// ---------------- launch -----------------------------------------------------
extern "C" void kernel_launch(void* const* d_in, const int* in_sizes, int n_in,
                              void* d_out, int out_size)
{
    (void)in_sizes; (void)n_in; (void)out_size;
    const float* X  = (const float*)d_in[0];
    const float* Wq = (const float*)d_in[1];
    const float* Wk = (const float*)d_in[2];
    const float* Wv = (const float*)d_in[3];
    const float* Wo = (const float*)d_in[4];

    float *q, *k, *v;
    __nv_bfloat16 *Xx, *attnx, *Wqx, *Wkx, *Wvx, *Wox;
    cudaGetSymbolAddress((void**)&q,     g_q);
    cudaGetSymbolAddress((void**)&k,     g_k);
    cudaGetSymbolAddress((void**)&v,     g_v);
    cudaGetSymbolAddress((void**)&Xx,    g_Xx);
    cudaGetSymbolAddress((void**)&attnx, g_attnx);
    cudaGetSymbolAddress((void**)&Wqx,   g_Wqx);
    cudaGetSymbolAddress((void**)&Wkx,   g_Wkx);
    cudaGetSymbolAddress((void**)&Wvx,   g_Wvx);
    cudaGetSymbolAddress((void**)&Wox,   g_Wox);

    const int M = BB * SS;        // 4096

    invf_kernel<<<1, 32>>>();

    expandA_kernel<<<(M * (DD / 8) + 255) / 256, 256>>>(X, Xx, M, DD);
    expandBt_kernel<<<((NH * HD) * (DD / 16) + 255) / 256, 256>>>(Wq, Wqx, DD, NH * HD);
    expandBt_kernel<<<((NKV * HD) * (DD / 16) + 255) / 256, 256>>>(Wk, Wkx, DD, NKV * HD);
    expandBt_kernel<<<((NKV * HD) * (DD / 16) + 255) / 256, 256>>>(Wv, Wvx, DD, NKV * HD);
    expandBt_kernel<<<(DD * (DD / 16) + 255) / 256, 256>>>(Wo, Wox, DD, DD);

    gemm_bf16_kernel<<<dim3((NH * HD) / 128,  M / 128), 256>>>(M, NH * HD,  Xx, Wqx, q);
    gemm_bf16_kernel<<<dim3((NKV * HD) / 128, M / 128), 256>>>(M, NKV * HD, Xx, Wkx, k);
    gemm_bf16_kernel<<<dim3((NKV * HD) / 128, M / 128), 256>>>(M, NKV * HD, Xx, Wvx, v);

    int nrope = M * (NH + NKV) * (HD / 2);
    rope_kernel<<<(nrope + 255) / 256, 256>>>(q, k, nrope);

    // tensor-core causal GQA flash attention; writes expanded attnx directly
    flash_mma_kernel<<<dim3(SS / 64, NH, BB), 128>>>(q, k, v, attnx);

    gemm_bf16_kernel<<<dim3(DD / 128, M / 128), 256>>>(M, DD, attnx, Wox, (float*)d_out);
}

// round 12
// speedup vs baseline: 1.5755x; 1.5755x over previous
#include <cuda_runtime.h>
#include <cuda_bf16.h>
#include <math.h>
#include <stdint.h>

// Problem constants
#define BB 2
#define SS 2048
#define DD 2048
#define NH 32
#define NKV 8
#define HD 64
#define GG (NH / NKV)   // 4
#define KX (3 * DD)     // expanded K = 6144
#define NQKV (NH * HD + 2 * NKV * HD)   // 3072 fused projection width
#define KOFF (NH * HD)                  // 2048: k region start in fused row
#define VOFF (NH * HD + NKV * HD)       // 2560: v region start

// ---------------- scratch (static __device__, no allocations) ----------------
__device__ float g_qkv[(size_t)BB * SS * NQKV];   // fused q|k|v rows
__device__ float g_attn[BB * SS * NH * HD];
__device__ float g_invf[HD / 2];

// split-bf16 expanded operands (INTERLEAVED triplet layout, as in R9):
//   A-side [M][3K]: cols (3k,3k+1,3k+2) = (hi, lo, hi)
//   B-side [N][3K]: cols (3k,3k+1,3k+2) = (hi, hi, lo)
__device__ __nv_bfloat16 g_Xx[(size_t)BB * SS * KX];
__device__ __nv_bfloat16 g_attnx[(size_t)BB * SS * KX];
__device__ __nv_bfloat16 g_Wqkvx[(size_t)NQKV * KX];   // fused Wq|Wk|Wv (transposed)
__device__ __nv_bfloat16 g_Wox[(size_t)DD * KX];

// ---------------- inv_freq table ---------------------------------------------
__global__ void invf_kernel()
{
    int i = threadIdx.x;
    if (i < HD / 2)
        g_invf[i] = (float)exp2(-(double)i * 0.41524101186092028); // log2(1e4)/32
}

// ---------------- split-bf16 expansion (R9 interleaved layout) ---------------
__global__ void expandA_kernel(const float* __restrict__ A,
                               __nv_bfloat16* __restrict__ Ax, int M, int K)
{
    int idx = blockIdx.x * blockDim.x + threadIdx.x;
    int total = M * (K / 4);
    if (idx >= total) return;
    int m  = idx / (K / 4);
    int k4 = (idx % (K / 4)) * 4;
    float4 x = *(const float4*)(A + (size_t)m * K + k4);
    float v[4] = {x.x, x.y, x.z, x.w};
    __align__(8) __nv_bfloat16 out[12];
#pragma unroll
    for (int j = 0; j < 4; j++) {
        __nv_bfloat16 hi = __float2bfloat16(v[j]);
        __nv_bfloat16 lo = __float2bfloat16(v[j] - __bfloat162float(hi));
        out[3 * j + 0] = hi;
        out[3 * j + 1] = lo;
        out[3 * j + 2] = hi;
    }
    uint2* dst = (uint2*)(Ax + (size_t)m * 3 * K + 3 * k4);
    const uint2* src = (const uint2*)out;
    dst[0] = src[0]; dst[1] = src[1]; dst[2] = src[2];
}

__global__ void expandBt_kernel(const float* __restrict__ B,
                                __nv_bfloat16* __restrict__ Bt, int K, int N)
{
    int idx = blockIdx.x * blockDim.x + threadIdx.x;
    int total = N * (K / 4);
    if (idx >= total) return;
    int n  = idx % N;
    int k4 = (idx / N) * 4;
    float v[4];
#pragma unroll
    for (int i = 0; i < 4; i++) v[i] = B[(size_t)(k4 + i) * N + n];
    __align__(8) __nv_bfloat16 out[12];
#pragma unroll
    for (int i = 0; i < 4; i++) {
        __nv_bfloat16 hi = __float2bfloat16(v[i]);
        __nv_bfloat16 lo = __float2bfloat16(v[i] - __bfloat162float(hi));
        out[3 * i + 0] = hi;
        out[3 * i + 1] = hi;
        out[3 * i + 2] = lo;
    }
    uint2* dst = (uint2*)(Bt + (size_t)n * 3 * K + 3 * k4);
    const uint2* src = (const uint2*)out;
    dst[0] = src[0]; dst[1] = src[1]; dst[2] = src[2];
}

// ---------------- helpers ----------------------------------------------------
__device__ __forceinline__ uint32_t smem_u32(const void* p) {
    uint32_t a;
    asm("{ .reg .u64 t; cvta.to.shared.u64 t, %1; cvt.u32.u64 %0, t; }"
        : "=r"(a) : "l"(p));
    return a;
}
#define CP_ASYNC16(dst, src) \
    asm volatile("cp.async.cg.shared.global [%0], [%1], 16;" \
                 :: "r"(dst), "l"(src) : "memory")
#define CP_COMMIT()  asm volatile("cp.async.commit_group;" ::: "memory")
#define CP_WAIT(n)   asm volatile("cp.async.wait_group %0;" :: "n"(n) : "memory")

#define MMA16816(C, A, B0, B1) \
    asm volatile("mma.sync.aligned.m16n8k16.row.col.f32.bf16.bf16.f32 " \
                 "{%0,%1,%2,%3}, {%4,%5,%6,%7}, {%8,%9}, {%0,%1,%2,%3};\n" \
                 : "+f"((C)[0]), "+f"((C)[1]), "+f"((C)[2]), "+f"((C)[3]) \
                 : "r"((A)[0]), "r"((A)[1]), "r"((A)[2]), "r"((A)[3]), \
                   "r"(B0), "r"(B1))

__device__ __forceinline__ uint32_t pack_bf16hi(float a, float b) {
    __nv_bfloat162 h;
    h.x = __float2bfloat16_rn(a);
    h.y = __float2bfloat16_rn(b);
    return *(uint32_t*)&h;
}
__device__ __forceinline__ uint32_t pack_bf16lo(float a, float b) {
    __nv_bfloat16 ha = __float2bfloat16_rn(a);
    __nv_bfloat16 hb = __float2bfloat16_rn(b);
    __nv_bfloat162 l;
    l.x = __float2bfloat16_rn(a - __bfloat162float(ha));
    l.y = __float2bfloat16_rn(b - __bfloat162float(hb));
    return *(uint32_t*)&l;
}

// fast e^x on the fma pipe (x <= 0), rel err ~3e-6
__device__ __forceinline__ float expf_fast(float x) {
    float y = x * 1.44269504088896f;
    y = fmaxf(y, -126.0f);
    float n = rintf(y);
    float f = y - n;
    float p = 1.33335581464e-3f;
    p = fmaf(p, f, 9.61812910763e-3f);
    p = fmaf(p, f, 5.55041086648e-2f);
    p = fmaf(p, f, 2.40226506959e-1f);
    p = fmaf(p, f, 6.93147180560e-1f);
    p = fmaf(p, f, 1.0f);
    float sc = __int_as_float(((int)n + 127) << 23);
    return p * sc;
}

// ---------------- mma.sync GEMM (unchanged mainloop) -------------------------
#define GST 40

__global__ __launch_bounds__(256)
void gemm_bf16_kernel(int M, int N, const __nv_bfloat16* __restrict__ A,
                      const __nv_bfloat16* __restrict__ Bt,
                      float* __restrict__ C)
{
    __shared__ __align__(16) __nv_bfloat16 sA[2][128 * GST];
    __shared__ __align__(16) __nv_bfloat16 sB[2][128 * GST];

    const int tid  = threadIdx.x;
    const int wid  = tid / 32;
    const int lane = tid % 32;
    const int warpM = wid / 2;
    const int warpN = wid % 2;
    const int g = lane >> 2;
    const int t = lane & 3;
    const int rowBase = warpM * 32;
    const int colBase = warpN * 64;

    const __nv_bfloat16* Ag = A  + (size_t)blockIdx.y * 128 * KX;
    const __nv_bfloat16* Bg = Bt + (size_t)blockIdx.x * 128 * KX;

    const int r0 = tid >> 2;
    const int c0 = (tid & 3) * 8;
    const int r1 = r0 + 64;

    const uint32_t sA0 = smem_u32(sA[0]), sA1 = smem_u32(sA[1]);
    const uint32_t sB0 = smem_u32(sB[0]), sB1 = smem_u32(sB[1]);
    const uint32_t dA0 = r0 * GST + c0, dA1 = r1 * GST + c0;

    float c[2][8][4];
#pragma unroll
    for (int mi = 0; mi < 2; mi++)
#pragma unroll
        for (int ni = 0; ni < 8; ni++)
#pragma unroll
            for (int r = 0; r < 4; r++) c[mi][ni][r] = 0.0f;

    const int NCH = KX / 32;

    CP_ASYNC16(sA0 + 2 * dA0, Ag + (size_t)r0 * KX + c0);
    CP_ASYNC16(sA0 + 2 * dA1, Ag + (size_t)r1 * KX + c0);
    CP_ASYNC16(sB0 + 2 * dA0, Bg + (size_t)r0 * KX + c0);
    CP_ASYNC16(sB0 + 2 * dA1, Bg + (size_t)r1 * KX + c0);
    CP_COMMIT();

    for (int ch = 0; ch < NCH; ch++) {
        if (ch + 1 < NCH) {
            const int kc = (ch + 1) * 32;
            const uint32_t a = ((ch + 1) & 1) ? sA1 : sA0;
            const uint32_t b = ((ch + 1) & 1) ? sB1 : sB0;
            CP_ASYNC16(a + 2 * dA0, Ag + (size_t)r0 * KX + kc + c0);
            CP_ASYNC16(a + 2 * dA1, Ag + (size_t)r1 * KX + kc + c0);
            CP_ASYNC16(b + 2 * dA0, Bg + (size_t)r0 * KX + kc + c0);
            CP_ASYNC16(b + 2 * dA1, Bg + (size_t)r1 * KX + kc + c0);
            CP_COMMIT();
            CP_WAIT(1);
        } else {
            CP_WAIT(0);
        }
        __syncthreads();

        const __nv_bfloat16* As = (ch & 1) ? sA[1] : sA[0];
        const __nv_bfloat16* Bs = (ch & 1) ? sB[1] : sB[0];

#pragma unroll
        for (int kk = 0; kk < 32; kk += 16) {
            uint32_t af[2][4], bfr[8][2];
#pragma unroll
            for (int mi = 0; mi < 2; mi++) {
                const __nv_bfloat16* p = As + (rowBase + mi * 16 + g) * GST + kk + 2 * t;
                af[mi][0] = *(const uint32_t*)p;
                af[mi][1] = *(const uint32_t*)(p + 8 * GST);
                af[mi][2] = *(const uint32_t*)(p + 8);
                af[mi][3] = *(const uint32_t*)(p + 8 * GST + 8);
            }
#pragma unroll
            for (int ni = 0; ni < 8; ni++) {
                const __nv_bfloat16* p = Bs + (colBase + ni * 8 + g) * GST + kk + 2 * t;
                bfr[ni][0] = *(const uint32_t*)p;
                bfr[ni][1] = *(const uint32_t*)(p + 8);
            }
#pragma unroll
            for (int mi = 0; mi < 2; mi++)
#pragma unroll
                for (int ni = 0; ni < 8; ni++)
                    MMA16816(c[mi][ni], af[mi], bfr[ni][0], bfr[ni][1]);
        }
        __syncthreads();
    }

    float* Cg = C + (size_t)blockIdx.y * 128 * N + (size_t)blockIdx.x * 128;
#pragma unroll
    for (int mi = 0; mi < 2; mi++) {
#pragma unroll
        for (int ni = 0; ni < 8; ni++) {
            int rr  = rowBase + mi * 16 + g;
            int col = colBase + ni * 8 + 2 * t;
            float2 lo = make_float2(c[mi][ni][0], c[mi][ni][1]);
            float2 hi = make_float2(c[mi][ni][2], c[mi][ni][3]);
            *(float2*)(Cg + (size_t)rr * N + col)       = lo;
            *(float2*)(Cg + (size_t)(rr + 8) * N + col) = hi;
        }
    }
}

// ---------------- RoPE (in-place on fused qkv) -------------------------------
__global__ void rope_kernel(float* __restrict__ qkv, int total)
{
    int idx = blockIdx.x * blockDim.x + threadIdx.x;
    if (idx >= total) return;

    const int PER_ROW = (NH + NKV) * (HD / 2);
    int row  = idx / PER_ROW;
    int rem  = idx % PER_ROW;
    int slot = rem / (HD / 2);
    int fi   = rem % (HD / 2);
    int spos = row % SS;

    float invf = g_invf[fi];
    float ang  = (float)spos * invf;

    float n = rintf(ang * 0.15915494309189535f);
    float r = fmaf(n, -6.28318548202514648f, ang);
    r       = fmaf(n,  1.74845553e-7f, r);
    float c  = __cosf(r);
    float sn = __sinf(r);

    float* base = qkv + (size_t)row * NQKV +
                  ((slot < NH) ? slot * HD : KOFF + (slot - NH) * HD);

    float x1 = base[fi];
    float x2 = base[fi + HD / 2];
    base[fi]          = x1 * c - x2 * sn;
    base[fi + HD / 2] = x2 * c + x1 * sn;
}

// ---------------- Tensor-core flash attention (split-bf16, causal, GQA) ------
#define FTS 72

__global__ __launch_bounds__(128)
void flash_mma_kernel(const float* __restrict__ QKV,
                      float* __restrict__ O)
{
    __shared__ __align__(16) __nv_bfloat16 sKh[64 * FTS];
    __shared__ __align__(16) __nv_bfloat16 sKl[64 * FTS];
    __shared__ __align__(16) __nv_bfloat16 sVh[64 * FTS];   // [d][key]
    __shared__ __align__(16) __nv_bfloat16 sVl[64 * FTS];

    const int tid = threadIdx.x;
    const int w    = tid >> 5;
    const int lane = tid & 31;
    const int g = lane >> 2, t = lane & 3;
    const int qt = blockIdx.x, h = blockIdx.y, b = blockIdx.z;
    const int rbase = qt * 64 + w * 16;
    const int kvh = h / GG;

    uint32_t qh[4][4], ql[4][4];
#pragma unroll
    for (int kk = 0; kk < 4; kk++) {
#pragma unroll
        for (int pt = 0; pt < 4; pt++) {
            int row = rbase + g + (pt & 1) * 8;
            int col = kk * 16 + 2 * t + (pt >> 1) * 8;
            const float* qp = QKV + (size_t)(b * SS + row) * NQKV + h * HD + col;
            float2 qv = *(const float2*)qp;
            float x0 = qv.x * 0.125f, x1 = qv.y * 0.125f;
            qh[kk][pt] = pack_bf16hi(x0, x1);
            ql[kk][pt] = pack_bf16lo(x0, x1);
        }
    }

    float o[8][4];
#pragma unroll
    for (int ni = 0; ni < 8; ni++)
#pragma unroll
        for (int j = 0; j < 4; j++) o[ni][j] = 0.0f;
    float m0 = -1e30f, m1 = -1e30f, l0 = 0.0f, l1 = 0.0f;

    const int ntiles = qt + 1;
    const int lr  = tid >> 1;
    const int lcg = (tid & 1) * 32;

    for (int kt = 0; kt < ntiles; kt++) {
        const int kbase = kt * 64;
        {
            const float* kp = QKV + (size_t)(b * SS + kbase + lr) * NQKV + KOFF + kvh * HD + lcg;
            const float* vp = QKV + (size_t)(b * SS + kbase + lr) * NQKV + VOFF + kvh * HD + lcg;
#pragma unroll
            for (int dd = 0; dd < 32; dd += 4) {
                float4 kv = *(const float4*)(kp + dd);
                float kvv[4] = {kv.x, kv.y, kv.z, kv.w};
                uint32_t* dsth = (uint32_t*)&sKh[lr * FTS + lcg + dd];
                uint32_t* dstl = (uint32_t*)&sKl[lr * FTS + lcg + dd];
                dsth[0] = pack_bf16hi(kvv[0], kvv[1]);
                dsth[1] = pack_bf16hi(kvv[2], kvv[3]);
                dstl[0] = pack_bf16lo(kvv[0], kvv[1]);
                dstl[1] = pack_bf16lo(kvv[2], kvv[3]);

                float4 vv = *(const float4*)(vp + dd);
                float vvv[4] = {vv.x, vv.y, vv.z, vv.w};
#pragma unroll
                for (int j = 0; j < 4; j++) {
                    __nv_bfloat16 hv = __float2bfloat16_rn(vvv[j]);
                    __nv_bfloat16 lv = __float2bfloat16_rn(vvv[j] - __bfloat162float(hv));
                    sVh[(lcg + dd + j) * FTS + lr] = hv;
                    sVl[(lcg + dd + j) * FTS + lr] = lv;
                }
            }
        }
        __syncthreads();

        float s[8][4];
#pragma unroll
        for (int ni = 0; ni < 8; ni++)
#pragma unroll
            for (int j = 0; j < 4; j++) s[ni][j] = 0.0f;

#pragma unroll
        for (int kk = 0; kk < 4; kk++) {
#pragma unroll
            for (int ni = 0; ni < 8; ni++) {
                const __nv_bfloat16* ph = sKh + (ni * 8 + g) * FTS + kk * 16 + 2 * t;
                const __nv_bfloat16* pl = sKl + (ni * 8 + g) * FTS + kk * 16 + 2 * t;
                uint32_t bh0 = *(const uint32_t*)ph;
                uint32_t bh1 = *(const uint32_t*)(ph + 8);
                uint32_t bl0 = *(const uint32_t*)pl;
                uint32_t bl1 = *(const uint32_t*)(pl + 8);
                MMA16816(s[ni], qh[kk], bh0, bh1);
                MMA16816(s[ni], qh[kk], bl0, bl1);
                MMA16816(s[ni], ql[kk], bh0, bh1);
            }
        }

        if (kt == ntiles - 1) {
#pragma unroll
            for (int ni = 0; ni < 8; ni++) {
#pragma unroll
                for (int j = 0; j < 4; j++) {
                    int key = kbase + ni * 8 + 2 * t + (j & 1);
                    int row = rbase + g + (j >> 1) * 8;
                    if (key > row) s[ni][j] = -1e30f;
                }
            }
        }

        float tm0 = -1e30f, tm1 = -1e30f;
#pragma unroll
        for (int ni = 0; ni < 8; ni++) {
            tm0 = fmaxf(tm0, fmaxf(s[ni][0], s[ni][1]));
            tm1 = fmaxf(tm1, fmaxf(s[ni][2], s[ni][3]));
        }
        tm0 = fmaxf(tm0, __shfl_xor_sync(0xFFFFFFFF, tm0, 1));
        tm0 = fmaxf(tm0, __shfl_xor_sync(0xFFFFFFFF, tm0, 2));
        tm1 = fmaxf(tm1, __shfl_xor_sync(0xFFFFFFFF, tm1, 1));
        tm1 = fmaxf(tm1, __shfl_xor_sync(0xFFFFFFFF, tm1, 2));

        float mn0 = fmaxf(m0, tm0), mn1 = fmaxf(m1, tm1);
        float c0 = expf_fast(m0 - mn0), c1 = expf_fast(m1 - mn1);
        l0 *= c0; l1 *= c1;
#pragma unroll
        for (int ni = 0; ni < 8; ni++) {
            o[ni][0] *= c0; o[ni][1] *= c0;
            o[ni][2] *= c1; o[ni][3] *= c1;
        }
        float rs0 = 0.0f, rs1 = 0.0f;
#pragma unroll
        for (int ni = 0; ni < 8; ni++) {
            s[ni][0] = expf_fast(s[ni][0] - mn0);
            s[ni][1] = expf_fast(s[ni][1] - mn0);
            s[ni][2] = expf_fast(s[ni][2] - mn1);
            s[ni][3] = expf_fast(s[ni][3] - mn1);
            rs0 += s[ni][0] + s[ni][1];
            rs1 += s[ni][2] + s[ni][3];
        }
        rs0 += __shfl_xor_sync(0xFFFFFFFF, rs0, 1);
        rs0 += __shfl_xor_sync(0xFFFFFFFF, rs0, 2);
        rs1 += __shfl_xor_sync(0xFFFFFFFF, rs1, 1);
        rs1 += __shfl_xor_sync(0xFFFFFFFF, rs1, 2);
        l0 += rs0; l1 += rs1;
        m0 = mn0; m1 = mn1;

#pragma unroll
        for (int kk = 0; kk < 4; kk++) {
            const float* s0 = s[2 * kk];
            const float* s1 = s[2 * kk + 1];
            uint32_t ah[4], al[4];
            ah[0] = pack_bf16hi(s0[0], s0[1]);  al[0] = pack_bf16lo(s0[0], s0[1]);
            ah[1] = pack_bf16hi(s0[2], s0[3]);  al[1] = pack_bf16lo(s0[2], s0[3]);
            ah[2] = pack_bf16hi(s1[0], s1[1]);  al[2] = pack_bf16lo(s1[0], s1[1]);
            ah[3] = pack_bf16hi(s1[2], s1[3]);  al[3] = pack_bf16lo(s1[2], s1[3]);
#pragma unroll
            for (int ni = 0; ni < 8; ni++) {
                const __nv_bfloat16* pvh = sVh + (ni * 8 + g) * FTS + kk * 16 + 2 * t;
                const __nv_bfloat16* pvl = sVl + (ni * 8 + g) * FTS + kk * 16 + 2 * t;
                uint32_t vh0 = *(const uint32_t*)pvh;
                uint32_t vh1 = *(const uint32_t*)(pvh + 8);
                uint32_t vl0 = *(const uint32_t*)pvl;
                uint32_t vl1 = *(const uint32_t*)(pvl + 8);
                MMA16816(o[ni], ah, vh0, vh1);
                MMA16816(o[ni], al, vh0, vh1);
                MMA16816(o[ni], ah, vl0, vl1);
            }
        }
        __syncthreads();
    }

    float i0 = 1.0f / l0, i1 = 1.0f / l1;
#pragma unroll
    for (int ni = 0; ni < 8; ni++) {
        float* op0 = O + (((size_t)(b * SS + rbase + g)) * NH + h) * HD + ni * 8 + 2 * t;
        float* op1 = O + (((size_t)(b * SS + rbase + g + 8)) * NH + h) * HD + ni * 8 + 2 * t;
        *(float2*)op0 = make_float2(o[ni][0] * i0, o[ni][1] * i0);
        *(float2*)op1 = make_float2(o[ni][2] * i1, o[ni][3] * i1);
    }
}

// ---------------- launch -----------------------------------------------------
extern "C" void kernel_launch(void* const* d_in, const int* in_sizes, int n_in,
                              void* d_out, int out_size)
{
    (void)in_sizes; (void)n_in; (void)out_size;
    const float* X  = (const float*)d_in[0];
    const float* Wq = (const float*)d_in[1];
    const float* Wk = (const float*)d_in[2];
    const float* Wv = (const float*)d_in[3];
    const float* Wo = (const float*)d_in[4];

    float *qkv, *attn;
    __nv_bfloat16 *Xx, *attnx, *Wqkvx, *Wox;
    cudaGetSymbolAddress((void**)&qkv,   g_qkv);
    cudaGetSymbolAddress((void**)&attn,  g_attn);
    cudaGetSymbolAddress((void**)&Xx,    g_Xx);
    cudaGetSymbolAddress((void**)&attnx, g_attnx);
    cudaGetSymbolAddress((void**)&Wqkvx, g_Wqkvx);
    cudaGetSymbolAddress((void**)&Wox,   g_Wox);

    const int M = BB * SS;        // 4096

    invf_kernel<<<1, 32>>>();

    // expansions (interleaved layout, as R9)
    expandA_kernel<<<(M * (DD / 4) + 255) / 256, 256>>>(X, Xx, M, DD);
    expandBt_kernel<<<((NH * HD) * (DD / 4) + 255) / 256, 256>>>(
        Wq, Wqkvx, DD, NH * HD);
    expandBt_kernel<<<((NKV * HD) * (DD / 4) + 255) / 256, 256>>>(
        Wk, Wqkvx + (size_t)KOFF * KX, DD, NKV * HD);
    expandBt_kernel<<<((NKV * HD) * (DD / 4) + 255) / 256, 256>>>(
        Wv, Wqkvx + (size_t)VOFF * KX, DD, NKV * HD);
    expandBt_kernel<<<(DD * (DD / 4) + 255) / 256, 256>>>(Wo, Wox, DD, DD);

    // fused QKV projection: one GEMM, N = 3072
    gemm_bf16_kernel<<<dim3(NQKV / 128, M / 128), 256>>>(M, NQKV, Xx, Wqkvx, qkv);

    // RoPE on fused buffer
    int nrope = M * (NH + NKV) * (HD / 2);
    rope_kernel<<<(nrope + 255) / 256, 256>>>(qkv, nrope);

    // tensor-core causal GQA flash attention
    flash_mma_kernel<<<dim3(SS / 64, NH, BB), 128>>>(qkv, attn);

    // output projection
    expandA_kernel<<<(M * (DD / 4) + 255) / 256, 256>>>(attn, attnx, M, DD);
    gemm_bf16_kernel<<<dim3(DD / 128, M / 128), 256>>>(M, DD, attnx, Wox, (float*)d_out);
}

// round 14
// speedup vs baseline: 1.5938x; 1.0116x over previous
#include <cuda_runtime.h>
#include <cuda_bf16.h>
#include <math.h>
#include <stdint.h>

// Problem constants
#define BB 2
#define SS 2048
#define DD 2048
#define NH 32
#define NKV 8
#define HD 64
#define GG (NH / NKV)   // 4
#define KX (3 * DD)     // expanded K = 6144
#define NQKV (NH * HD + 2 * NKV * HD)   // 3072 fused projection width
#define KOFF (NH * HD)                  // 2048: k region start in fused row
#define VOFF (NH * HD + NKV * HD)       // 2560: v region start

// ---------------- scratch (static __device__, no allocations) ----------------
__device__ float g_qkv[(size_t)BB * SS * NQKV];   // fused q|k|v rows
__device__ float g_attn[BB * SS * NH * HD];
__device__ float g_invf[HD / 2];

// split-bf16 expanded operands (INTERLEAVED triplet layout):
//   A-side [M][3K]: cols (3k,3k+1,3k+2) = (hi, lo, hi)
//   B-side [N][3K]: cols (3k,3k+1,3k+2) = (hi, hi, lo)
__device__ __nv_bfloat16 g_Xx[(size_t)BB * SS * KX];
__device__ __nv_bfloat16 g_attnx[(size_t)BB * SS * KX];
__device__ __nv_bfloat16 g_Wqkvx[(size_t)NQKV * KX];   // fused Wq|Wk|Wv (transposed)
__device__ __nv_bfloat16 g_Wox[(size_t)DD * KX];

// ---------------- inv_freq table ---------------------------------------------
__global__ void invf_kernel()
{
    int i = threadIdx.x;
    if (i < HD / 2)
        g_invf[i] = (float)exp2(-(double)i * 0.41524101186092028); // log2(1e4)/32
}

// ---------------- split-bf16 expansion (interleaved layout) ------------------
__global__ void expandA_kernel(const float* __restrict__ A,
                               __nv_bfloat16* __restrict__ Ax, int M, int K)
{
    int idx = blockIdx.x * blockDim.x + threadIdx.x;
    int total = M * (K / 4);
    if (idx >= total) return;
    int m  = idx / (K / 4);
    int k4 = (idx % (K / 4)) * 4;
    float4 x = *(const float4*)(A + (size_t)m * K + k4);
    float v[4] = {x.x, x.y, x.z, x.w};
    __align__(8) __nv_bfloat16 out[12];
#pragma unroll
    for (int j = 0; j < 4; j++) {
        __nv_bfloat16 hi = __float2bfloat16(v[j]);
        __nv_bfloat16 lo = __float2bfloat16(v[j] - __bfloat162float(hi));
        out[3 * j + 0] = hi;
        out[3 * j + 1] = lo;
        out[3 * j + 2] = hi;
    }
    uint2* dst = (uint2*)(Ax + (size_t)m * 3 * K + 3 * k4);
    const uint2* src = (const uint2*)out;
    dst[0] = src[0]; dst[1] = src[1]; dst[2] = src[2];
}

__global__ void expandBt_kernel(const float* __restrict__ B,
                                __nv_bfloat16* __restrict__ Bt, int K, int N)
{
    int idx = blockIdx.x * blockDim.x + threadIdx.x;
    int total = N * (K / 4);
    if (idx >= total) return;
    int n  = idx % N;
    int k4 = (idx / N) * 4;
    float v[4];
#pragma unroll
    for (int i = 0; i < 4; i++) v[i] = B[(size_t)(k4 + i) * N + n];
    __align__(8) __nv_bfloat16 out[12];
#pragma unroll
    for (int i = 0; i < 4; i++) {
        __nv_bfloat16 hi = __float2bfloat16(v[i]);
        __nv_bfloat16 lo = __float2bfloat16(v[i] - __bfloat162float(hi));
        out[3 * i + 0] = hi;
        out[3 * i + 1] = hi;
        out[3 * i + 2] = lo;
    }
    uint2* dst = (uint2*)(Bt + (size_t)n * 3 * K + 3 * k4);
    const uint2* src = (const uint2*)out;
    dst[0] = src[0]; dst[1] = src[1]; dst[2] = src[2];
}

// ---------------- helpers ----------------------------------------------------
__device__ __forceinline__ uint32_t smem_u32(const void* p) {
    uint32_t a;
    asm("{ .reg .u64 t; cvta.to.shared.u64 t, %1; cvt.u32.u64 %0, t; }"
        : "=r"(a) : "l"(p));
    return a;
}
#define CP_ASYNC16(dst, src) \
    asm volatile("cp.async.cg.shared.global [%0], [%1], 16;" \
                 :: "r"(dst), "l"(src) : "memory")
#define CP_COMMIT()  asm volatile("cp.async.commit_group;" ::: "memory")
#define CP_WAIT(n)   asm volatile("cp.async.wait_group %0;" :: "n"(n) : "memory")

#define MMA16816(C, A, B0, B1) \
    asm volatile("mma.sync.aligned.m16n8k16.row.col.f32.bf16.bf16.f32 " \
                 "{%0,%1,%2,%3}, {%4,%5,%6,%7}, {%8,%9}, {%0,%1,%2,%3};\n" \
                 : "+f"((C)[0]), "+f"((C)[1]), "+f"((C)[2]), "+f"((C)[3]) \
                 : "r"((A)[0]), "r"((A)[1]), "r"((A)[2]), "r"((A)[3]), \
                   "r"(B0), "r"(B1))

__device__ __forceinline__ uint32_t pack_bf16hi(float a, float b) {
    __nv_bfloat162 h;
    h.x = __float2bfloat16_rn(a);
    h.y = __float2bfloat16_rn(b);
    return *(uint32_t*)&h;
}
__device__ __forceinline__ uint32_t pack_bf16lo(float a, float b) {
    __nv_bfloat16 ha = __float2bfloat16_rn(a);
    __nv_bfloat16 hb = __float2bfloat16_rn(b);
    __nv_bfloat162 l;
    l.x = __float2bfloat16_rn(a - __bfloat162float(ha));
    l.y = __float2bfloat16_rn(b - __bfloat162float(hb));
    return *(uint32_t*)&l;
}

// fast e^x on the fma pipe (x <= 0), rel err ~3e-6
__device__ __forceinline__ float expf_fast(float x) {
    float y = x * 1.44269504088896f;
    y = fmaxf(y, -126.0f);
    float n = rintf(y);
    float f = y - n;
    float p = 1.33335581464e-3f;
    p = fmaf(p, f, 9.61812910763e-3f);
    p = fmaf(p, f, 5.55041086648e-2f);
    p = fmaf(p, f, 2.40226506959e-1f);
    p = fmaf(p, f, 6.93147180560e-1f);
    p = fmaf(p, f, 1.0f);
    float sc = __int_as_float(((int)n + 127) << 23);
    return p * sc;
}

// ---------------- mma.sync GEMM: ONE barrier per K-chunk ---------------------
// 2-stage cp.async double buffer. The barrier at chunk ch proves all warps
// finished computing chunk ch-1, which is exactly when buffer (ch+1)&1
// (consumed at ch-1) becomes safe to refill -> next-chunk loads are issued
// AFTER the single barrier; the trailing barrier is gone.
#define GST 40

__global__ __launch_bounds__(256)
void gemm_bf16_kernel(int M, int N, const __nv_bfloat16* __restrict__ A,
                      const __nv_bfloat16* __restrict__ Bt,
                      float* __restrict__ C)
{
    __shared__ __align__(16) __nv_bfloat16 sA[2][128 * GST];
    __shared__ __align__(16) __nv_bfloat16 sB[2][128 * GST];

    const int tid  = threadIdx.x;
    const int wid  = tid / 32;
    const int lane = tid % 32;
    const int warpM = wid / 2;
    const int warpN = wid % 2;
    const int g = lane >> 2;
    const int t = lane & 3;
    const int rowBase = warpM * 32;
    const int colBase = warpN * 64;

    const __nv_bfloat16* Ag = A  + (size_t)blockIdx.y * 128 * KX;
    const __nv_bfloat16* Bg = Bt + (size_t)blockIdx.x * 128 * KX;

    const int r0 = tid >> 2;
    const int c0 = (tid & 3) * 8;
    const int r1 = r0 + 64;

    const uint32_t sA0 = smem_u32(sA[0]), sA1 = smem_u32(sA[1]);
    const uint32_t sB0 = smem_u32(sB[0]), sB1 = smem_u32(sB[1]);
    const uint32_t dA0 = r0 * GST + c0, dA1 = r1 * GST + c0;

    float c[2][8][4];
#pragma unroll
    for (int mi = 0; mi < 2; mi++)
#pragma unroll
        for (int ni = 0; ni < 8; ni++)
#pragma unroll
            for (int r = 0; r < 4; r++) c[mi][ni][r] = 0.0f;

    const int NCH = KX / 32;

    // prologue: stage 0
    CP_ASYNC16(sA0 + 2 * dA0, Ag + (size_t)r0 * KX + c0);
    CP_ASYNC16(sA0 + 2 * dA1, Ag + (size_t)r1 * KX + c0);
    CP_ASYNC16(sB0 + 2 * dA0, Bg + (size_t)r0 * KX + c0);
    CP_ASYNC16(sB0 + 2 * dA1, Bg + (size_t)r1 * KX + c0);
    CP_COMMIT();

    for (int ch = 0; ch < NCH; ch++) {
        CP_WAIT(0);            // chunk ch's loads have landed
        __syncthreads();       // ... and all warps finished computing ch-1

        if (ch + 1 < NCH) {    // refill the buffer consumed at ch-1
            const int kc = (ch + 1) * 32;
            const uint32_t a = ((ch + 1) & 1) ? sA1 : sA0;
            const uint32_t b = ((ch + 1) & 1) ? sB1 : sB0;
            CP_ASYNC16(a + 2 * dA0, Ag + (size_t)r0 * KX + kc + c0);
            CP_ASYNC16(a + 2 * dA1, Ag + (size_t)r1 * KX + kc + c0);
            CP_ASYNC16(b + 2 * dA0, Bg + (size_t)r0 * KX + kc + c0);
            CP_ASYNC16(b + 2 * dA1, Bg + (size_t)r1 * KX + kc + c0);
            CP_COMMIT();
        }

        const __nv_bfloat16* As = (ch & 1) ? sA[1] : sA[0];
        const __nv_bfloat16* Bs = (ch & 1) ? sB[1] : sB[0];

#pragma unroll
        for (int kk = 0; kk < 32; kk += 16) {
            uint32_t af[2][4], bfr[8][2];
#pragma unroll
            for (int mi = 0; mi < 2; mi++) {
                const __nv_bfloat16* p = As + (rowBase + mi * 16 + g) * GST + kk + 2 * t;
                af[mi][0] = *(const uint32_t*)p;
                af[mi][1] = *(const uint32_t*)(p + 8 * GST);
                af[mi][2] = *(const uint32_t*)(p + 8);
                af[mi][3] = *(const uint32_t*)(p + 8 * GST + 8);
            }
#pragma unroll
            for (int ni = 0; ni < 8; ni++) {
                const __nv_bfloat16* p = Bs + (colBase + ni * 8 + g) * GST + kk + 2 * t;
                bfr[ni][0] = *(const uint32_t*)p;
                bfr[ni][1] = *(const uint32_t*)(p + 8);
            }
#pragma unroll
            for (int mi = 0; mi < 2; mi++)
#pragma unroll
                for (int ni = 0; ni < 8; ni++)
                    MMA16816(c[mi][ni], af[mi], bfr[ni][0], bfr[ni][1]);
        }
    }

    float* Cg = C + (size_t)blockIdx.y * 128 * N + (size_t)blockIdx.x * 128;
#pragma unroll
    for (int mi = 0; mi < 2; mi++) {
#pragma unroll
        for (int ni = 0; ni < 8; ni++) {
            int rr  = rowBase + mi * 16 + g;
            int col = colBase + ni * 8 + 2 * t;
            float2 lo = make_float2(c[mi][ni][0], c[mi][ni][1]);
            float2 hi = make_float2(c[mi][ni][2], c[mi][ni][3]);
            *(float2*)(Cg + (size_t)rr * N + col)       = lo;
            *(float2*)(Cg + (size_t)(rr + 8) * N + col) = hi;
        }
    }
}

// ---------------- RoPE (in-place on fused qkv) -------------------------------
__global__ void rope_kernel(float* __restrict__ qkv, int total)
{
    int idx = blockIdx.x * blockDim.x + threadIdx.x;
    if (idx >= total) return;

    const int PER_ROW = (NH + NKV) * (HD / 2);
    int row  = idx / PER_ROW;
    int rem  = idx % PER_ROW;
    int slot = rem / (HD / 2);
    int fi   = rem % (HD / 2);
    int spos = row % SS;

    float invf = g_invf[fi];
    float ang  = (float)spos * invf;

    float n = rintf(ang * 0.15915494309189535f);
    float r = fmaf(n, -6.28318548202514648f, ang);
    r       = fmaf(n,  1.74845553e-7f, r);
    float c  = __cosf(r);
    float sn = __sinf(r);

    float* base = qkv + (size_t)row * NQKV +
                  ((slot < NH) ? slot * HD : KOFF + (slot - NH) * HD);

    float x1 = base[fi];
    float x2 = base[fi + HD / 2];
    base[fi]          = x1 * c - x2 * sn;
    base[fi + HD / 2] = x2 * c + x1 * sn;
}

// ---------------- Tensor-core flash attention (split-bf16, causal, GQA) ------
#define FTS 72

__global__ __launch_bounds__(128)
void flash_mma_kernel(const float* __restrict__ QKV,
                      float* __restrict__ O)
{
    __shared__ __align__(16) __nv_bfloat16 sKh[64 * FTS];
    __shared__ __align__(16) __nv_bfloat16 sKl[64 * FTS];
    __shared__ __align__(16) __nv_bfloat16 sVh[64 * FTS];   // [d][key]
    __shared__ __align__(16) __nv_bfloat16 sVl[64 * FTS];

    const int tid = threadIdx.x;
    const int w    = tid >> 5;
    const int lane = tid & 31;
    const int g = lane >> 2, t = lane & 3;
    const int qt = blockIdx.x, h = blockIdx.y, b = blockIdx.z;
    const int rbase = qt * 64 + w * 16;
    const int kvh = h / GG;

    uint32_t qh[4][4], ql[4][4];
#pragma unroll
    for (int kk = 0; kk < 4; kk++) {
#pragma unroll
        for (int pt = 0; pt < 4; pt++) {
            int row = rbase + g + (pt & 1) * 8;
            int col = kk * 16 + 2 * t + (pt >> 1) * 8;
            const float* qp = QKV + (size_t)(b * SS + row) * NQKV + h * HD + col;
            float2 qv = *(const float2*)qp;
            float x0 = qv.x * 0.125f, x1 = qv.y * 0.125f;
            qh[kk][pt] = pack_bf16hi(x0, x1);
            ql[kk][pt] = pack_bf16lo(x0, x1);
        }
    }

    float o[8][4];
#pragma unroll
    for (int ni = 0; ni < 8; ni++)
#pragma unroll
        for (int j = 0; j < 4; j++) o[ni][j] = 0.0f;
    float m0 = -1e30f, m1 = -1e30f, l0 = 0.0f, l1 = 0.0f;

    const int ntiles = qt + 1;
    const int lr  = tid >> 1;
    const int lcg = (tid & 1) * 32;

    for (int kt = 0; kt < ntiles; kt++) {
        const int kbase = kt * 64;
        {
            const float* kp = QKV + (size_t)(b * SS + kbase + lr) * NQKV + KOFF + kvh * HD + lcg;
            const float* vp = QKV + (size_t)(b * SS + kbase + lr) * NQKV + VOFF + kvh * HD + lcg;
#pragma unroll
            for (int dd = 0; dd < 32; dd += 4) {
                float4 kv = *(const float4*)(kp + dd);
                float kvv[4] = {kv.x, kv.y, kv.z, kv.w};
                uint32_t* dsth = (uint32_t*)&sKh[lr * FTS + lcg + dd];
                uint32_t* dstl = (uint32_t*)&sKl[lr * FTS + lcg + dd];
                dsth[0] = pack_bf16hi(kvv[0], kvv[1]);
                dsth[1] = pack_bf16hi(kvv[2], kvv[3]);
                dstl[0] = pack_bf16lo(kvv[0], kvv[1]);
                dstl[1] = pack_bf16lo(kvv[2], kvv[3]);

                float4 vv = *(const float4*)(vp + dd);
                float vvv[4] = {vv.x, vv.y, vv.z, vv.w};
#pragma unroll
                for (int j = 0; j < 4; j++) {
                    __nv_bfloat16 hv = __float2bfloat16_rn(vvv[j]);
                    __nv_bfloat16 lv = __float2bfloat16_rn(vvv[j] - __bfloat162float(hv));
                    sVh[(lcg + dd + j) * FTS + lr] = hv;
                    sVl[(lcg + dd + j) * FTS + lr] = lv;
                }
            }
        }
        __syncthreads();

        float s[8][4];
#pragma unroll
        for (int ni = 0; ni < 8; ni++)
#pragma unroll
            for (int j = 0; j < 4; j++) s[ni][j] = 0.0f;

#pragma unroll
        for (int kk = 0; kk < 4; kk++) {
#pragma unroll
            for (int ni = 0; ni < 8; ni++) {
                const __nv_bfloat16* ph = sKh + (ni * 8 + g) * FTS + kk * 16 + 2 * t;
                const __nv_bfloat16* pl = sKl + (ni * 8 + g) * FTS + kk * 16 + 2 * t;
                uint32_t bh0 = *(const uint32_t*)ph;
                uint32_t bh1 = *(const uint32_t*)(ph + 8);
                uint32_t bl0 = *(const uint32_t*)pl;
                uint32_t bl1 = *(const uint32_t*)(pl + 8);
                MMA16816(s[ni], qh[kk], bh0, bh1);
                MMA16816(s[ni], qh[kk], bl0, bl1);
                MMA16816(s[ni], ql[kk], bh0, bh1);
            }
        }

        if (kt == ntiles - 1) {
#pragma unroll
            for (int ni = 0; ni < 8; ni++) {
#pragma unroll
                for (int j = 0; j < 4; j++) {
                    int key = kbase + ni * 8 + 2 * t + (j & 1);
                    int row = rbase + g + (j >> 1) * 8;
                    if (key > row) s[ni][j] = -1e30f;
                }
            }
        }

        float tm0 = -1e30f, tm1 = -1e30f;
#pragma unroll
        for (int ni = 0; ni < 8; ni++) {
            tm0 = fmaxf(tm0, fmaxf(s[ni][0], s[ni][1]));
            tm1 = fmaxf(tm1, fmaxf(s[ni][2], s[ni][3]));
        }
        tm0 = fmaxf(tm0, __shfl_xor_sync(0xFFFFFFFF, tm0, 1));
        tm0 = fmaxf(tm0, __shfl_xor_sync(0xFFFFFFFF, tm0, 2));
        tm1 = fmaxf(tm1, __shfl_xor_sync(0xFFFFFFFF, tm1, 1));
        tm1 = fmaxf(tm1, __shfl_xor_sync(0xFFFFFFFF, tm1, 2));

        float mn0 = fmaxf(m0, tm0), mn1 = fmaxf(m1, tm1);
        float c0 = expf_fast(m0 - mn0), c1 = expf_fast(m1 - mn1);
        l0 *= c0; l1 *= c1;
#pragma unroll
        for (int ni = 0; ni < 8; ni++) {
            o[ni][0] *= c0; o[ni][1] *= c0;
            o[ni][2] *= c1; o[ni][3] *= c1;
        }
        float rs0 = 0.0f, rs1 = 0.0f;
#pragma unroll
        for (int ni = 0; ni < 8; ni++) {
            s[ni][0] = expf_fast(s[ni][0] - mn0);
            s[ni][1] = expf_fast(s[ni][1] - mn0);
            s[ni][2] = expf_fast(s[ni][2] - mn1);
            s[ni][3] = expf_fast(s[ni][3] - mn1);
            rs0 += s[ni][0] + s[ni][1];
            rs1 += s[ni][2] + s[ni][3];
        }
        rs0 += __shfl_xor_sync(0xFFFFFFFF, rs0, 1);
        rs0 += __shfl_xor_sync(0xFFFFFFFF, rs0, 2);
        rs1 += __shfl_xor_sync(0xFFFFFFFF, rs1, 1);
        rs1 += __shfl_xor_sync(0xFFFFFFFF, rs1, 2);
        l0 += rs0; l1 += rs1;
        m0 = mn0; m1 = mn1;

#pragma unroll
        for (int kk = 0; kk < 4; kk++) {
            const float* s0 = s[2 * kk];
            const float* s1 = s[2 * kk + 1];
            uint32_t ah[4], al[4];
            ah[0] = pack_bf16hi(s0[0], s0[1]);  al[0] = pack_bf16lo(s0[0], s0[1]);
            ah[1] = pack_bf16hi(s0[2], s0[3]);  al[1] = pack_bf16lo(s0[2], s0[3]);
            ah[2] = pack_bf16hi(s1[0], s1[1]);  al[2] = pack_bf16lo(s1[0], s1[1]);
            ah[3] = pack_bf16hi(s1[2], s1[3]);  al[3] = pack_bf16lo(s1[2], s1[3]);
#pragma unroll
            for (int ni = 0; ni < 8; ni++) {
                const __nv_bfloat16* pvh = sVh + (ni * 8 + g) * FTS + kk * 16 + 2 * t;
                const __nv_bfloat16* pvl = sVl + (ni * 8 + g) * FTS + kk * 16 + 2 * t;
                uint32_t vh0 = *(const uint32_t*)pvh;
                uint32_t vh1 = *(const uint32_t*)(pvh + 8);
                uint32_t vl0 = *(const uint32_t*)pvl;
                uint32_t vl1 = *(const uint32_t*)(pvl + 8);
                MMA16816(o[ni], ah, vh0, vh1);
                MMA16816(o[ni], al, vh0, vh1);
                MMA16816(o[ni], ah, vl0, vl1);
            }
        }
        __syncthreads();
    }

    float i0 = 1.0f / l0, i1 = 1.0f / l1;
#pragma unroll
    for (int ni = 0; ni < 8; ni++) {
        float* op0 = O + (((size_t)(b * SS + rbase + g)) * NH + h) * HD + ni * 8 + 2 * t;
        float* op1 = O + (((size_t)(b * SS + rbase + g + 8)) * NH + h) * HD + ni * 8 + 2 * t;
        *(float2*)op0 = make_float2(o[ni][0] * i0, o[ni][1] * i0);
        *(float2*)op1 = make_float2(o[ni][2] * i1, o[ni][3] * i1);
    }
}

// ---------------- launch -----------------------------------------------------
extern "C" void kernel_launch(void* const* d_in, const int* in_sizes, int n_in,
                              void* d_out, int out_size)
{
    (void)in_sizes; (void)n_in; (void)out_size;
    const float* X  = (const float*)d_in[0];
    const float* Wq = (const float*)d_in[1];
    const float* Wk = (const float*)d_in[2];
    const float* Wv = (const float*)d_in[3];
    const float* Wo = (const float*)d_in[4];

    float *qkv, *attn;
    __nv_bfloat16 *Xx, *attnx, *Wqkvx, *Wox;
    cudaGetSymbolAddress((void**)&qkv,   g_qkv);
    cudaGetSymbolAddress((void**)&attn,  g_attn);
    cudaGetSymbolAddress((void**)&Xx,    g_Xx);
    cudaGetSymbolAddress((void**)&attnx, g_attnx);
    cudaGetSymbolAddress((void**)&Wqkvx, g_Wqkvx);
    cudaGetSymbolAddress((void**)&Wox,   g_Wox);

    const int M = BB * SS;        // 4096

    invf_kernel<<<1, 32>>>();

    // expansions (interleaved layout)
    expandA_kernel<<<(M * (DD / 4) + 255) / 256, 256>>>(X, Xx, M, DD);
    expandBt_kernel<<<((NH * HD) * (DD / 4) + 255) / 256, 256>>>(
        Wq, Wqkvx, DD, NH * HD);
    expandBt_kernel<<<((NKV * HD) * (DD / 4) + 255) / 256, 256>>>(
        Wk, Wqkvx + (size_t)KOFF * KX, DD, NKV * HD);
    expandBt_kernel<<<((NKV * HD) * (DD / 4) + 255) / 256, 256>>>(
        Wv, Wqkvx + (size_t)VOFF * KX, DD, NKV * HD);
    expandBt_kernel<<<(DD * (DD / 4) + 255) / 256, 256>>>(Wo, Wox, DD, DD);

    // fused QKV projection: one GEMM, N = 3072
    gemm_bf16_kernel<<<dim3(NQKV / 128, M / 128), 256>>>(M, NQKV, Xx, Wqkvx, qkv);

    // RoPE on fused buffer
    int nrope = M * (NH + NKV) * (HD / 2);
    rope_kernel<<<(nrope + 255) / 256, 256>>>(qkv, nrope);

    // tensor-core causal GQA flash attention
    flash_mma_kernel<<<dim3(SS / 64, NH, BB), 128>>>(qkv, attn);

    // output projection
    expandA_kernel<<<(M * (DD / 4) + 255) / 256, 256>>>(attn, attnx, M, DD);
    gemm_bf16_kernel<<<dim3(DD / 128, M / 128), 256>>>(M, DD, attnx, Wox, (float*)d_out);
}